// round 4
// baseline (speedup 1.0000x reference)
#include <cuda_runtime.h>
#include <math.h>

// Problem constants (fixed by the reference build)
#define MM   4096      // checks
#define NN   8192      // variables
#define BB   256       // batch
#define EE   32768     // edges  (NN * DV)
#define N_ITERS 10
#define ALPHA_C 0.8f
#define CLAMP_V 20.0f
#define PAD_BIG_C 1.0e6f

// ---------------- static device scratch (no allocations allowed) -----------
__device__ float g_ctv  [EE * BB];   // check->var messages, edge-major [E,B]
__device__ float g_vext [NN * BB];   // llr + sum of incoming ctv, [N,B]
__device__ float g_llr_t[NN * BB];   // transposed channel LLR, [N,B]
__device__ float g_ssign[MM * BB];   // 1-2*syndrome, [M,B]
__device__ float g_hard [NN * BB];   // hard decisions, [N,B] (for parity)
__device__ int   g_deg  [MM];        // check degrees
__device__ int   g_perm [MM];        // degree-sorted check permutation
__device__ int2  g_ev   [MM * 32];   // per check-slot: (edge, var), padded
__device__ int   g_maxdc;            // runtime max_dc (stashed by prep)

// ---------------- helpers ----------------------------------------------------
__device__ __forceinline__ float clampv(float x) {
    return fminf(fmaxf(x, -CLAMP_V), CLAMP_V);
}

// ---------------- kernels ---------------------------------------------------
// Device globals referenced only from device code (host shadow is not a dev ptr).

// Transpose INPUT [rows, cols] into device global [cols, rows].
// DST: 0 -> g_llr_t AND g_vext (iter-0 vext == llr), 1 -> g_ssign (1-2x).
template<int DST>
__global__ void k_tr_in(const float* __restrict__ in, int rows, int cols)
{
    __shared__ float tile[32][33];
    int c0 = blockIdx.x * 32;
    int r0 = blockIdx.y * 32;
    int c = c0 + threadIdx.x;
    #pragma unroll
    for (int i = 0; i < 32; i += 8) {
        int r = r0 + threadIdx.y + i;
        tile[threadIdx.y + i][threadIdx.x] = in[(size_t)r * cols + c];
    }
    __syncthreads();
    int oc = r0 + threadIdx.x;            // output column (= input row)
    #pragma unroll
    for (int i = 0; i < 32; i += 8) {
        int orow = c0 + threadIdx.y + i;  // output row (= input col)
        size_t oi = (size_t)orow * rows + oc;
        float v = tile[threadIdx.x][threadIdx.y + i];
        if (DST == 0) { g_llr_t[oi] = v; g_vext[oi] = v; }
        else          { g_ssign[oi] = 1.0f - 2.0f * v; }
    }
}

// Prep: per-check degree + packed (edge, var) slot table (padded with (0,0)).
__global__ void k_prep(const float* __restrict__ check_mask,
                       const int* __restrict__ check_adj,
                       const int* __restrict__ var_idx,
                       int max_dc)
{
    int c = blockIdx.x * blockDim.x + threadIdx.x;
    if (c >= MM) return;
    if (c == 0) g_maxdc = max_dc;
    const float* m   = check_mask + (size_t)c * max_dc;
    const int*   adj = check_adj  + (size_t)c * max_dc;
    int d = 0;
    for (int j = 0; j < max_dc; j++) {
        bool on = (__ldg(m + j) != 0.0f);
        int  e  = on ? __ldg(adj + j) : 0;
        int  v  = on ? __ldg(var_idx + e) : 0;
        g_ev[c * 32 + j] = make_int2(e, v);
        d += on;
    }
    g_deg[c] = d;
}

// Counting sort of checks by degree (single block). Order within a bucket is
// arbitrary (atomic) — results are order-independent per check.
__global__ void k_sortperm()
{
    __shared__ int base[64];
    int t = threadIdx.x;
    if (t < 64) base[t] = 0;
    __syncthreads();
    for (int c = t; c < MM; c += blockDim.x)
        atomicAdd(&base[min(g_deg[c], 63)], 1);
    __syncthreads();
    if (t == 0) {
        int s = 0;
        for (int i = 0; i < 64; i++) { int h = base[i]; base[i] = s; s += h; }
    }
    __syncthreads();
    for (int c = t; c < MM; c += blockDim.x) {
        int p = atomicAdd(&base[min(g_deg[c], 63)], 1);
        g_perm[p] = c;
    }
}

// Var side: vext[v] = llr[v] + (((a+b)+c)+d)  — EXACT reference order.
// Block = 256 threads = 4 vars x 64 float4-lanes.
__global__ void k_varsum(const int* __restrict__ var_adj)
{
    int t = threadIdx.x;
    int v = blockIdx.x * 4 + (t >> 6);
    int j = t & 63;
    int4 e = __ldg((const int4*)var_adj + v);
    float4 a = ((const float4*)(g_ctv + (size_t)e.x * BB))[j];
    float4 b = ((const float4*)(g_ctv + (size_t)e.y * BB))[j];
    float4 c = ((const float4*)(g_ctv + (size_t)e.z * BB))[j];
    float4 d = ((const float4*)(g_ctv + (size_t)e.w * BB))[j];
    float4 l = ((const float4*)(g_llr_t + (size_t)v * BB))[j];
    float4 s;
    s.x = l.x + (((a.x + b.x) + c.x) + d.x);
    s.y = l.y + (((a.y + b.y) + c.y) + d.y);
    s.z = l.z + (((a.z + b.z) + c.z) + d.z);
    s.w = l.w + (((a.w + b.w) + c.w) + d.w);
    ((float4*)(g_vext + (size_t)v * BB))[j] = s;
}

// Check side: min-sum update. Block = 256 threads = 4 checks x 64 float4-lanes.
// Checks taken through the degree-sorted permutation for intra-block balance.
template<bool FIRST>
__global__ void k_checkupd()
{
    int t = threadIdx.x;
    int c = g_perm[blockIdx.x * 4 + (t >> 6)];
    int j = t & 63;
    int deg = g_deg[c];
    if (deg == 0) return;
    const int2* ev = g_ev + c * 32;

    float4 sg = ((const float4*)(g_ssign + (size_t)c * BB))[j];
    float4 m1, m2;
    if (deg == 1) {
        // reference pads with global edge 0: seed = |vtc(edge0)| + 1e6
        int v0 = g_ev[0].y;
        float4 x0 = ((const float4*)(g_vext + (size_t)v0 * BB))[j];
        if (!FIRST) {
            float4 c0 = ((const float4*)g_ctv)[j];
            x0.x -= c0.x; x0.y -= c0.y; x0.z -= c0.z; x0.w -= c0.w;
        }
        m1.x = fabsf(clampv(x0.x)) + PAD_BIG_C;
        m1.y = fabsf(clampv(x0.y)) + PAD_BIG_C;
        m1.z = fabsf(clampv(x0.z)) + PAD_BIG_C;
        m1.w = fabsf(clampv(x0.w)) + PAD_BIG_C;
    } else {
        m1.x = m1.y = m1.z = m1.w = 1.0e30f;   // pad can never win for deg>=2
    }
    m2 = m1;

    // pass 1: sign product + two smallest magnitudes
    #pragma unroll 4
    for (int p = 0; p < deg; p++) {
        int2 s = ev[p];
        float4 x = ((const float4*)(g_vext + (size_t)s.y * BB))[j];
        if (!FIRST) {
            float4 o = ((const float4*)(g_ctv + (size_t)s.x * BB))[j];
            x.x -= o.x; x.y -= o.y; x.z -= o.z; x.w -= o.w;
        }
        x.x = clampv(x.x); x.y = clampv(x.y); x.z = clampv(x.z); x.w = clampv(x.w);
        if (x.x < 0.0f) sg.x = -sg.x;
        if (x.y < 0.0f) sg.y = -sg.y;
        if (x.z < 0.0f) sg.z = -sg.z;
        if (x.w < 0.0f) sg.w = -sg.w;
        float a;
        a = fabsf(x.x); if (a < m1.x) { m2.x = m1.x; m1.x = a; } else if (a < m2.x) m2.x = a;
        a = fabsf(x.y); if (a < m1.y) { m2.y = m1.y; m1.y = a; } else if (a < m2.y) m2.y = a;
        a = fabsf(x.z); if (a < m1.z) { m2.z = m1.z; m1.z = a; } else if (a < m2.z) m2.z = a;
        a = fabsf(x.w); if (a < m1.w) { m2.w = m1.w; m1.w = a; } else if (a < m2.w) m2.w = a;
    }

    // pass 2: recompute x (L1/L2-warm), write new messages
    #pragma unroll 4
    for (int p = 0; p < deg; p++) {
        int2 s = ev[p];
        float4 x = ((const float4*)(g_vext + (size_t)s.y * BB))[j];
        if (!FIRST) {
            float4 o = ((const float4*)(g_ctv + (size_t)s.x * BB))[j];
            x.x -= o.x; x.y -= o.y; x.z -= o.z; x.w -= o.w;
        }
        x.x = clampv(x.x); x.y = clampv(x.y); x.z = clampv(x.z); x.w = clampv(x.w);
        float4 out;
        {
            float a = fabsf(x.x);
            float m = (fabsf(a - m1.x) < 1e-9f) ? m2.x : m1.x;
            out.x = ALPHA_C * sg.x * ((x.x < 0.0f) ? -m : m);
        }
        {
            float a = fabsf(x.y);
            float m = (fabsf(a - m1.y) < 1e-9f) ? m2.y : m1.y;
            out.y = ALPHA_C * sg.y * ((x.y < 0.0f) ? -m : m);
        }
        {
            float a = fabsf(x.z);
            float m = (fabsf(a - m1.z) < 1e-9f) ? m2.z : m1.z;
            out.z = ALPHA_C * sg.z * ((x.z < 0.0f) ? -m : m);
        }
        {
            float a = fabsf(x.w);
            float m = (fabsf(a - m1.w) < 1e-9f) ? m2.w : m1.w;
            out.w = ALPHA_C * sg.w * ((x.w < 0.0f) ? -m : m);
        }
        ((float4*)(g_ctv + (size_t)s.x * BB))[j] = out;
    }
}

// Final: read g_vext (= total_llr), write marginals + hard to d_out [B,N],
// and hard to g_hard [N,B] for the parity kernel.
__global__ void k_out(float* __restrict__ out_marg, float* __restrict__ out_hard)
{
    __shared__ float tile[32][33];
    int c0 = blockIdx.x * 32;   // batch tile
    int r0 = blockIdx.y * 32;   // var tile
    int c = c0 + threadIdx.x;
    #pragma unroll
    for (int i = 0; i < 32; i += 8) {
        int r = r0 + threadIdx.y + i;
        float t = g_vext[(size_t)r * BB + c];
        tile[threadIdx.y + i][threadIdx.x] = t;
        float marg = 1.0f / (1.0f + expf(t));
        g_hard[(size_t)r * BB + c] = (marg > 0.5f) ? 1.0f : 0.0f;
    }
    __syncthreads();
    int oc = r0 + threadIdx.x;            // var index in output
    #pragma unroll
    for (int i = 0; i < 32; i += 8) {
        int orow = c0 + threadIdx.y + i;  // batch index in output
        float t = tile[threadIdx.x][threadIdx.y + i];
        float marg = 1.0f / (1.0f + expf(t));
        size_t oi = (size_t)orow * NN + oc;
        out_marg[oi] = marg;
        out_hard[oi] = (marg > 0.5f) ? 1.0f : 0.0f;
    }
}

__global__ void k_initconv(float* __restrict__ conv)
{
    conv[threadIdx.x] = 1.0f;
}

// Parity per (check, batch-quad): mismatch -> converged[b] = 0.
__global__ void k_parity(float* __restrict__ conv)
{
    int t = threadIdx.x;
    int c = blockIdx.x * 4 + (t >> 6);
    int j = t & 63;
    int deg = g_deg[c];
    const int2* ev = g_ev + c * 32;
    int p0 = 0, p1 = 0, p2 = 0, p3 = 0;
    for (int p = 0; p < deg; p++) {
        int v = ev[p].y;
        float4 h = ((const float4*)(g_hard + (size_t)v * BB))[j];
        p0 += (int)h.x; p1 += (int)h.y; p2 += (int)h.z; p3 += (int)h.w;
    }
    float4 sg = ((const float4*)(g_ssign + (size_t)c * BB))[j];
    if ((p0 & 1) != (sg.x < 0.0f ? 1 : 0)) conv[j * 4 + 0] = 0.0f;
    if ((p1 & 1) != (sg.y < 0.0f ? 1 : 0)) conv[j * 4 + 1] = 0.0f;
    if ((p2 & 1) != (sg.z < 0.0f ? 1 : 0)) conv[j * 4 + 2] = 0.0f;
    if ((p3 & 1) != (sg.w < 0.0f ? 1 : 0)) conv[j * 4 + 3] = 0.0f;
}

// ---------------- launch ----------------------------------------------------

extern "C" void kernel_launch(void* const* d_in, const int* in_sizes, int n_in,
                              void* d_out, int out_size)
{
    const float* syndrome   = (const float*)d_in[0];   // [B, M]
    const float* llr        = (const float*)d_in[1];   // [B, N]
    const int*   var_adj    = (const int*)  d_in[2];   // [N, 4]
    const int*   check_adj  = (const int*)  d_in[4];   // [M, max_dc]
    const float* check_mask = (const float*)d_in[5];   // [M, max_dc]
    const int*   var_idx    = (const int*)  d_in[6];   // [E]

    const int max_dc = in_sizes[4] / MM;   // <= 32 for this code family
    float* out = (float*)d_out;
    size_t bn = (size_t)BB * NN;
    float* out_marg = out;            // [B, N]
    float* out_hard = out + bn;       // [B, N]
    float* out_conv = out + 2 * bn;   // [B]

    dim3 tb(32, 8);
    k_tr_in<0><<<dim3(NN / 32, BB / 32), tb>>>(llr, BB, NN);      // -> llr_t + vext
    k_tr_in<1><<<dim3(MM / 32, BB / 32), tb>>>(syndrome, BB, MM); // -> ssign
    k_prep<<<(MM + 255) / 256, 256>>>(check_mask, check_adj, var_idx, max_dc);
    k_sortperm<<<1, 1024>>>();

    k_checkupd<true><<<MM / 4, 256>>>();
    for (int it = 1; it < N_ITERS; it++) {
        k_varsum<<<NN / 4, 256>>>(var_adj);
        k_checkupd<false><<<MM / 4, 256>>>();
    }
    k_varsum<<<NN / 4, 256>>>(var_adj);   // final vext = total_llr

    k_out<<<dim3(BB / 32, NN / 32), tb>>>(out_marg, out_hard);
    k_initconv<<<1, BB>>>(out_conv);
    k_parity<<<MM / 4, 256>>>(out_conv);
}

// round 5
// speedup vs baseline: 1.0358x; 1.0358x over previous
#include <cuda_runtime.h>
#include <math.h>

// Problem constants (fixed by the reference build)
#define MM   4096      // checks
#define NN   8192      // variables
#define BB   256       // batch
#define EE   32768     // edges  (NN * DV)
#define N_ITERS 10
#define ALPHA_C 0.8f
#define CLAMP_V 20.0f
#define PAD_BIG_C 1.0e6f

// ---------------- static device scratch (no allocations allowed) -----------
__device__ float g_ctv  [EE * BB];   // check->var messages, edge-major [E,B]
__device__ float g_vtc  [EE * BB];   // clamped var->check messages, [E,B]
__device__ float g_llr_t[NN * BB];   // transposed channel LLR, [N,B]
__device__ float g_ssign[MM * BB];   // 1-2*syndrome, [M,B]
__device__ float g_hard [NN * BB];   // hard decisions, [N,B] (for parity)
__device__ int   g_deg  [MM];        // check degrees
__device__ int2  g_ev   [MM * 32];   // per check: compacted (edge, var) slots

// ---------------- helpers ----------------------------------------------------
__device__ __forceinline__ float clampv(float x) {
    return fminf(fmaxf(x, -CLAMP_V), CLAMP_V);
}

// ---------------- kernels ---------------------------------------------------
// Device globals referenced only from device code (host shadow is not a dev ptr).

// Transpose llr [B,N] -> g_llr_t [N,B]; also seed g_vtc (iter0 ctv==0 so
// vtc[e] = clamp(llr[v]) for each of v's 4 edges).
__global__ void k_tr_llr(const float* __restrict__ in,
                         const int* __restrict__ var_adj)
{
    __shared__ float tile[32][33];
    int c0 = blockIdx.x * 32;   // N tile
    int r0 = blockIdx.y * 32;   // B tile
    int c = c0 + threadIdx.x;
    #pragma unroll
    for (int i = 0; i < 32; i += 8) {
        int r = r0 + threadIdx.y + i;
        tile[threadIdx.y + i][threadIdx.x] = in[(size_t)r * NN + c];
    }
    __syncthreads();
    int oc = r0 + threadIdx.x;            // batch index
    #pragma unroll
    for (int i = 0; i < 32; i += 8) {
        int v = c0 + threadIdx.y + i;     // var index (uniform per warp)
        float x = tile[threadIdx.x][threadIdx.y + i];
        g_llr_t[(size_t)v * BB + oc] = x;
        float cv = clampv(x);
        int4 e = __ldg((const int4*)var_adj + v);
        g_vtc[(size_t)e.x * BB + oc] = cv;
        g_vtc[(size_t)e.y * BB + oc] = cv;
        g_vtc[(size_t)e.z * BB + oc] = cv;
        g_vtc[(size_t)e.w * BB + oc] = cv;
    }
}

// Transpose syndrome [B,M] -> g_ssign [M,B] with 1-2x.
__global__ void k_tr_syn(const float* __restrict__ in)
{
    __shared__ float tile[32][33];
    int c0 = blockIdx.x * 32;
    int r0 = blockIdx.y * 32;
    int c = c0 + threadIdx.x;
    #pragma unroll
    for (int i = 0; i < 32; i += 8) {
        int r = r0 + threadIdx.y + i;
        tile[threadIdx.y + i][threadIdx.x] = in[(size_t)r * MM + c];
    }
    __syncthreads();
    int oc = r0 + threadIdx.x;
    #pragma unroll
    for (int i = 0; i < 32; i += 8) {
        int orow = c0 + threadIdx.y + i;
        g_ssign[(size_t)orow * BB + oc] =
            1.0f - 2.0f * tile[threadIdx.x][threadIdx.y + i];
    }
}

// Prep: per-check degree + COMPACTED (edge, var) slot table.
__global__ void k_prep(const float* __restrict__ check_mask,
                       const int* __restrict__ check_adj,
                       const int* __restrict__ var_idx,
                       int max_dc)
{
    int c = blockIdx.x * blockDim.x + threadIdx.x;
    if (c >= MM) return;
    const float* m   = check_mask + (size_t)c * max_dc;
    const int*   adj = check_adj  + (size_t)c * max_dc;
    int d = 0;
    for (int j = 0; j < max_dc; j++) {
        if (__ldg(m + j) != 0.0f) {
            int e = __ldg(adj + j);
            g_ev[c * 32 + d] = make_int2(e, __ldg(var_idx + e));
            d++;
        }
    }
    g_deg[c] = d;
}

// Check side: min-sum update from the single vtc stream.
// Block = 256 threads = 4 checks x 64 float4-lanes (2 warps per check,
// so degree variance causes no warp divergence).
__global__ void k_checkupd()
{
    int t = threadIdx.x;
    int c = blockIdx.x * 4 + (t >> 6);
    int j = t & 63;
    int deg = g_deg[c];
    if (deg == 0) return;
    const int2* ev = g_ev + c * 32;

    float4 sg = ((const float4*)(g_ssign + (size_t)c * BB))[j];
    float4 m1, m2;
    if (deg == 1) {
        // reference pads with global edge 0: seed = |vtc(edge0)| + 1e6
        float4 x0 = ((const float4*)g_vtc)[j];   // row 0, already clamped
        m1.x = fabsf(x0.x) + PAD_BIG_C;
        m1.y = fabsf(x0.y) + PAD_BIG_C;
        m1.z = fabsf(x0.z) + PAD_BIG_C;
        m1.w = fabsf(x0.w) + PAD_BIG_C;
    } else {
        m1.x = m1.y = m1.z = m1.w = 1.0e30f;   // pad can never win for deg>=2
    }
    m2 = m1;

    // pass 1: sign product + two smallest magnitudes
    #pragma unroll 4
    for (int p = 0; p < deg; p++) {
        int e = ev[p].x;
        float4 x = ((const float4*)(g_vtc + (size_t)e * BB))[j];
        if (x.x < 0.0f) sg.x = -sg.x;
        if (x.y < 0.0f) sg.y = -sg.y;
        if (x.z < 0.0f) sg.z = -sg.z;
        if (x.w < 0.0f) sg.w = -sg.w;
        float a;
        a = fabsf(x.x); if (a < m1.x) { m2.x = m1.x; m1.x = a; } else if (a < m2.x) m2.x = a;
        a = fabsf(x.y); if (a < m1.y) { m2.y = m1.y; m1.y = a; } else if (a < m2.y) m2.y = a;
        a = fabsf(x.z); if (a < m1.z) { m2.z = m1.z; m1.z = a; } else if (a < m2.z) m2.z = a;
        a = fabsf(x.w); if (a < m1.w) { m2.w = m1.w; m1.w = a; } else if (a < m2.w) m2.w = a;
    }

    // pass 2: reload vtc (L1/L2-warm), write new messages
    #pragma unroll 4
    for (int p = 0; p < deg; p++) {
        int e = ev[p].x;
        float4 x = ((const float4*)(g_vtc + (size_t)e * BB))[j];
        float4 out;
        {
            float a = fabsf(x.x);
            float m = (fabsf(a - m1.x) < 1e-9f) ? m2.x : m1.x;
            out.x = ALPHA_C * sg.x * ((x.x < 0.0f) ? -m : m);
        }
        {
            float a = fabsf(x.y);
            float m = (fabsf(a - m1.y) < 1e-9f) ? m2.y : m1.y;
            out.y = ALPHA_C * sg.y * ((x.y < 0.0f) ? -m : m);
        }
        {
            float a = fabsf(x.z);
            float m = (fabsf(a - m1.z) < 1e-9f) ? m2.z : m1.z;
            out.z = ALPHA_C * sg.z * ((x.z < 0.0f) ? -m : m);
        }
        {
            float a = fabsf(x.w);
            float m = (fabsf(a - m1.w) < 1e-9f) ? m2.w : m1.w;
            out.w = ALPHA_C * sg.w * ((x.w < 0.0f) ? -m : m);
        }
        ((float4*)(g_ctv + (size_t)e * BB))[j] = out;
    }
}

// Var side: compute vext = llr + (((a+b)+c)+d) (EXACT reference order),
// then write clamped vtc[e] = clamp(vext - ctv[e]) for each of the 4 edges.
// Block = 256 threads = 4 vars x 64 float4-lanes.
__global__ void k_varsum(const int* __restrict__ var_adj)
{
    int t = threadIdx.x;
    int v = blockIdx.x * 4 + (t >> 6);
    int j = t & 63;
    int4 e = __ldg((const int4*)var_adj + v);
    float4 a = ((const float4*)(g_ctv + (size_t)e.x * BB))[j];
    float4 b = ((const float4*)(g_ctv + (size_t)e.y * BB))[j];
    float4 c = ((const float4*)(g_ctv + (size_t)e.z * BB))[j];
    float4 d = ((const float4*)(g_ctv + (size_t)e.w * BB))[j];
    float4 l = ((const float4*)(g_llr_t + (size_t)v * BB))[j];
    float4 s;
    s.x = l.x + (((a.x + b.x) + c.x) + d.x);
    s.y = l.y + (((a.y + b.y) + c.y) + d.y);
    s.z = l.z + (((a.z + b.z) + c.z) + d.z);
    s.w = l.w + (((a.w + b.w) + c.w) + d.w);
    float4 o;
    o.x = clampv(s.x - a.x); o.y = clampv(s.y - a.y);
    o.z = clampv(s.z - a.z); o.w = clampv(s.w - a.w);
    ((float4*)(g_vtc + (size_t)e.x * BB))[j] = o;
    o.x = clampv(s.x - b.x); o.y = clampv(s.y - b.y);
    o.z = clampv(s.z - b.z); o.w = clampv(s.w - b.w);
    ((float4*)(g_vtc + (size_t)e.y * BB))[j] = o;
    o.x = clampv(s.x - c.x); o.y = clampv(s.y - c.y);
    o.z = clampv(s.z - c.z); o.w = clampv(s.w - c.w);
    ((float4*)(g_vtc + (size_t)e.z * BB))[j] = o;
    o.x = clampv(s.x - d.x); o.y = clampv(s.y - d.y);
    o.z = clampv(s.z - d.z); o.w = clampv(s.w - d.w);
    ((float4*)(g_vtc + (size_t)e.w * BB))[j] = o;
}

// Final (fused): total_llr = llr + sum(ctv); marginals + hard to d_out [B,N];
// hard also to g_hard [N,B]; block (0,0) initializes conv to 1.
__global__ void k_out(const int* __restrict__ var_adj,
                      float* __restrict__ out_marg,
                      float* __restrict__ out_hard,
                      float* __restrict__ conv)
{
    __shared__ float tile[32][33];
    int c0 = blockIdx.x * 32;   // batch tile
    int r0 = blockIdx.y * 32;   // var tile
    int c = c0 + threadIdx.x;   // batch index
    if (blockIdx.x == 0 && blockIdx.y == 0) {
        int t = threadIdx.y * 32 + threadIdx.x;
        conv[t] = 1.0f;
    }
    #pragma unroll
    for (int i = 0; i < 32; i += 8) {
        int v = r0 + threadIdx.y + i;      // uniform per warp
        int4 e = __ldg((const int4*)var_adj + v);
        float a = g_ctv[(size_t)e.x * BB + c];
        float b = g_ctv[(size_t)e.y * BB + c];
        float d0 = g_ctv[(size_t)e.z * BB + c];
        float d1 = g_ctv[(size_t)e.w * BB + c];
        float l = g_llr_t[(size_t)v * BB + c];
        float t = l + (((a + b) + d0) + d1);
        tile[threadIdx.y + i][threadIdx.x] = t;
        float marg = 1.0f / (1.0f + expf(t));
        g_hard[(size_t)v * BB + c] = (marg > 0.5f) ? 1.0f : 0.0f;
    }
    __syncthreads();
    int oc = r0 + threadIdx.x;            // var index in output
    #pragma unroll
    for (int i = 0; i < 32; i += 8) {
        int orow = c0 + threadIdx.y + i;  // batch index in output
        float t = tile[threadIdx.x][threadIdx.y + i];
        float marg = 1.0f / (1.0f + expf(t));
        size_t oi = (size_t)orow * NN + oc;
        out_marg[oi] = marg;
        out_hard[oi] = (marg > 0.5f) ? 1.0f : 0.0f;
    }
}

// Parity per (check, batch-quad): mismatch -> converged[b] = 0.
__global__ void k_parity(float* __restrict__ conv)
{
    int t = threadIdx.x;
    int c = blockIdx.x * 4 + (t >> 6);
    int j = t & 63;
    int deg = g_deg[c];
    const int2* ev = g_ev + c * 32;
    int p0 = 0, p1 = 0, p2 = 0, p3 = 0;
    for (int p = 0; p < deg; p++) {
        int v = ev[p].y;
        float4 h = ((const float4*)(g_hard + (size_t)v * BB))[j];
        p0 += (int)h.x; p1 += (int)h.y; p2 += (int)h.z; p3 += (int)h.w;
    }
    float4 sg = ((const float4*)(g_ssign + (size_t)c * BB))[j];
    if ((p0 & 1) != (sg.x < 0.0f ? 1 : 0)) conv[j * 4 + 0] = 0.0f;
    if ((p1 & 1) != (sg.y < 0.0f ? 1 : 0)) conv[j * 4 + 1] = 0.0f;
    if ((p2 & 1) != (sg.z < 0.0f ? 1 : 0)) conv[j * 4 + 2] = 0.0f;
    if ((p3 & 1) != (sg.w < 0.0f ? 1 : 0)) conv[j * 4 + 3] = 0.0f;
}

// ---------------- launch ----------------------------------------------------

extern "C" void kernel_launch(void* const* d_in, const int* in_sizes, int n_in,
                              void* d_out, int out_size)
{
    const float* syndrome   = (const float*)d_in[0];   // [B, M]
    const float* llr        = (const float*)d_in[1];   // [B, N]
    const int*   var_adj    = (const int*)  d_in[2];   // [N, 4]
    const int*   check_adj  = (const int*)  d_in[4];   // [M, max_dc]
    const float* check_mask = (const float*)d_in[5];   // [M, max_dc]
    const int*   var_idx    = (const int*)  d_in[6];   // [E]

    const int max_dc = in_sizes[4] / MM;   // <= 32 for this code family
    float* out = (float*)d_out;
    size_t bn = (size_t)BB * NN;
    float* out_marg = out;            // [B, N]
    float* out_hard = out + bn;       // [B, N]
    float* out_conv = out + 2 * bn;   // [B]

    dim3 tb(32, 8);
    k_tr_llr<<<dim3(NN / 32, BB / 32), tb>>>(llr, var_adj);  // llr_t + iter0 vtc
    k_tr_syn<<<dim3(MM / 32, BB / 32), tb>>>(syndrome);      // ssign
    k_prep<<<(MM + 255) / 256, 256>>>(check_mask, check_adj, var_idx, max_dc);

    k_checkupd<<<MM / 4, 256>>>();
    for (int it = 1; it < N_ITERS; it++) {
        k_varsum<<<NN / 4, 256>>>(var_adj);
        k_checkupd<<<MM / 4, 256>>>();
    }

    k_out<<<dim3(BB / 32, NN / 32), tb>>>(var_adj, out_marg, out_hard, out_conv);
    k_parity<<<MM / 4, 256>>>(out_conv);
}